// round 4
// baseline (speedup 1.0000x reference)
#include <cuda_runtime.h>

#define B_TOT   32768
#define IN_DIM  256
#define H_DIM   256
#define K1      512     // IN + H
#define BM      32      // batch rows per CTA
#define KT      32      // K tile
#define NTHREADS 256

typedef unsigned long long u64;

__device__ __forceinline__ u64 pk2(float lo, float hi) {
    u64 r; asm("mov.b64 %0, {%1,%2};" : "=l"(r) : "f"(lo), "f"(hi)); return r;
}
__device__ __forceinline__ float2 up2(u64 v) {
    float2 r; asm("mov.b64 {%0,%1}, %2;" : "=f"(r.x), "=f"(r.y) : "l"(v)); return r;
}
__device__ __forceinline__ void fma2(u64& d, u64 a, u64 b) {
    asm("fma.rn.f32x2 %0, %1, %2, %0;" : "+l"(d) : "l"(a), "l"(b));
}
__device__ __forceinline__ float sigmoidf_(float v) {
    return 1.0f / (1.0f + __expf(-v));
}

// Fused GRU cell:
//   r = sigmoid([x|h] @ wr + br)
//   z = sigmoid([x|h] @ wz + bz)
//   g = tanh((r*h) @ whh + x @ whx + bh)
//   h_out = h + z*(g - h)
__global__ void __launch_bounds__(NTHREADS)
gru_fused_kernel(const float* __restrict__ x,   const float* __restrict__ hp,
                 const float* __restrict__ wr,  const float* __restrict__ wz,
                 const float* __restrict__ whh, const float* __restrict__ whx,
                 const float* __restrict__ br,  const float* __restrict__ bz,
                 const float* __restrict__ bh,  float* __restrict__ out)
{
    extern __shared__ float sm[];
    float* sA  = sm;                         // [BM][K1]   : cols 0..255 = x, 256..511 = h
    float* sW  = sm + BM * K1;               // [2][KT][H_DIM]
    float* sRH = sW + 2 * KT * H_DIM;        // [BM][H_DIM]: r*h

    const int tid  = threadIdx.x;
    const int tx   = tid & 31;               // 32 column groups
    const int ty   = tid >> 5;               // 8 row groups (rows ty, ty+8, ty+16, ty+24)
    const int row0 = blockIdx.x * BM;

    // ---- stage A = [x | h] tile ----
    for (int i = tid; i < BM * (IN_DIM / 4); i += NTHREADS) {
        int r = i / (IN_DIM / 4), c = (i % (IN_DIM / 4)) * 4;
        *(float4*)&sA[r * K1 + c]          = *(const float4*)&x [(row0 + r) * IN_DIM + c];
        *(float4*)&sA[r * K1 + IN_DIM + c] = *(const float4*)&hp[(row0 + r) * H_DIM  + c];
    }
    __syncthreads();

    // ---- GEMM1: both gates share the A operand ----
    u64 accr[4][4], accz[4][4];
    #pragma unroll
    for (int i = 0; i < 4; i++)
        #pragma unroll
        for (int p = 0; p < 4; p++) { accr[i][p] = 0ull; accz[i][p] = 0ull; }

    for (int kt = 0; kt < K1; kt += KT) {
        for (int i = tid; i < KT * (H_DIM / 4); i += NTHREADS) {
            int kr = i / (H_DIM / 4), c = (i % (H_DIM / 4)) * 4;
            *(float4*)&sW[kr * H_DIM + c]                = *(const float4*)&wr[(kt + kr) * H_DIM + c];
            *(float4*)&sW[KT * H_DIM + kr * H_DIM + c]   = *(const float4*)&wz[(kt + kr) * H_DIM + c];
        }
        __syncthreads();
        #pragma unroll 4
        for (int kk = 0; kk < KT; kk++) {
            u64 av[4];
            #pragma unroll
            for (int i = 0; i < 4; i++) {
                float a = sA[(ty + 8 * i) * K1 + kt + kk];
                av[i] = pk2(a, a);
            }
            #pragma unroll
            for (int p = 0; p < 4; p++) {
                int col = 2 * tx + 64 * p;
                float2 w1 = *(float2*)&sW[kk * H_DIM + col];
                float2 w2 = *(float2*)&sW[KT * H_DIM + kk * H_DIM + col];
                u64 bw1 = pk2(w1.x, w1.y), bw2 = pk2(w2.x, w2.y);
                #pragma unroll
                for (int i = 0; i < 4; i++) {
                    fma2(accr[i][p], av[i], bw1);
                    fma2(accz[i][p], av[i], bw2);
                }
            }
        }
        __syncthreads();
    }

    // ---- epilogue 1: r,z; keep z in regs; write r*h to smem ----
    float2 zk[4][4];
    #pragma unroll
    for (int p = 0; p < 4; p++) {
        int col = 2 * tx + 64 * p;
        float br0 = br[col], br1 = br[col + 1];
        float bz0 = bz[col], bz1 = bz[col + 1];
        #pragma unroll
        for (int i = 0; i < 4; i++) {
            int r = ty + 8 * i;
            float2 cr = up2(accr[i][p]);
            float2 cz = up2(accz[i][p]);
            float rg0 = sigmoidf_(cr.x + br0);
            float rg1 = sigmoidf_(cr.y + br1);
            zk[i][p].x = sigmoidf_(cz.x + bz0);
            zk[i][p].y = sigmoidf_(cz.y + bz1);
            float2 h2 = *(float2*)&sA[r * K1 + IN_DIM + col];
            *(float2*)&sRH[r * H_DIM + col] = make_float2(rg0 * h2.x, rg1 * h2.y);
        }
    }
    __syncthreads();

    // ---- GEMM2: x @ whx + (r*h) @ whh ----
    u64 acc2[4][4];
    #pragma unroll
    for (int i = 0; i < 4; i++)
        #pragma unroll
        for (int p = 0; p < 4; p++) acc2[i][p] = 0ull;

    // part A: x @ whx
    for (int kt = 0; kt < IN_DIM; kt += KT) {
        for (int i = tid; i < KT * (H_DIM / 4); i += NTHREADS) {
            int kr = i / (H_DIM / 4), c = (i % (H_DIM / 4)) * 4;
            *(float4*)&sW[kr * H_DIM + c] = *(const float4*)&whx[(kt + kr) * H_DIM + c];
        }
        __syncthreads();
        #pragma unroll 4
        for (int kk = 0; kk < KT; kk++) {
            u64 av[4];
            #pragma unroll
            for (int i = 0; i < 4; i++) {
                float a = sA[(ty + 8 * i) * K1 + kt + kk];
                av[i] = pk2(a, a);
            }
            #pragma unroll
            for (int p = 0; p < 4; p++) {
                int col = 2 * tx + 64 * p;
                float2 w1 = *(float2*)&sW[kk * H_DIM + col];
                u64 bw1 = pk2(w1.x, w1.y);
                #pragma unroll
                for (int i = 0; i < 4; i++) fma2(acc2[i][p], av[i], bw1);
            }
        }
        __syncthreads();
    }
    // part B: (r*h) @ whh
    for (int kt = 0; kt < H_DIM; kt += KT) {
        for (int i = tid; i < KT * (H_DIM / 4); i += NTHREADS) {
            int kr = i / (H_DIM / 4), c = (i % (H_DIM / 4)) * 4;
            *(float4*)&sW[kr * H_DIM + c] = *(const float4*)&whh[(kt + kr) * H_DIM + c];
        }
        __syncthreads();
        #pragma unroll 4
        for (int kk = 0; kk < KT; kk++) {
            u64 av[4];
            #pragma unroll
            for (int i = 0; i < 4; i++) {
                float a = sRH[(ty + 8 * i) * H_DIM + kt + kk];
                av[i] = pk2(a, a);
            }
            #pragma unroll
            for (int p = 0; p < 4; p++) {
                int col = 2 * tx + 64 * p;
                float2 w1 = *(float2*)&sW[kk * H_DIM + col];
                u64 bw1 = pk2(w1.x, w1.y);
                #pragma unroll
                for (int i = 0; i < 4; i++) fma2(acc2[i][p], av[i], bw1);
            }
        }
        __syncthreads();
    }

    // ---- final epilogue: g = tanh(c2 + bh); h_out = h + z*(g - h) ----
    #pragma unroll
    for (int p = 0; p < 4; p++) {
        int col = 2 * tx + 64 * p;
        float bh0 = bh[col], bh1 = bh[col + 1];
        #pragma unroll
        for (int i = 0; i < 4; i++) {
            int r = ty + 8 * i;
            float2 c2 = up2(acc2[i][p]);
            float g0 = tanhf(c2.x + bh0);
            float g1 = tanhf(c2.y + bh1);
            float2 h2 = *(float2*)&sA[r * K1 + IN_DIM + col];
            float o0 = h2.x + zk[i][p].x * (g0 - h2.x);
            float o1 = h2.y + zk[i][p].y * (g1 - h2.y);
            *(float2*)&out[(row0 + r) * H_DIM + col] = make_float2(o0, o1);
        }
    }
}

extern "C" void kernel_launch(void* const* d_in, const int* in_sizes, int n_in,
                              void* d_out, int out_size)
{
    const float* x   = (const float*)d_in[0];
    const float* hp  = (const float*)d_in[1];
    const float* wr  = (const float*)d_in[2];
    const float* wz  = (const float*)d_in[3];
    const float* whh = (const float*)d_in[4];
    const float* whx = (const float*)d_in[5];
    const float* br  = (const float*)d_in[6];
    const float* bz  = (const float*)d_in[7];
    const float* bh  = (const float*)d_in[8];

    size_t smem = (size_t)(BM * K1 + 2 * KT * H_DIM + BM * H_DIM) * sizeof(float); // 160 KB
    cudaFuncSetAttribute(gru_fused_kernel,
                         cudaFuncAttributeMaxDynamicSharedMemorySize, (int)smem);
    gru_fused_kernel<<<B_TOT / BM, NTHREADS, smem>>>(
        x, hp, wr, wz, whh, whx, br, bz, bh, (float*)d_out);
}

// round 6
// speedup vs baseline: 1.2579x; 1.2579x over previous
#include <cuda_runtime.h>

#define IN_DIM  256
#define H_DIM   256
#define K1      512
#define BM      64          // batch rows per CTA
#define KT      16          // K tile
#define NT      512         // threads
#define NTILES  32          // K1/KT
#define W1TILE  (2*KT*H_DIM)     // 8192 floats per GEMM1 buffer (wr|wz)
#define SA_FLOATS (BM*K1)        // 32768 floats

typedef unsigned long long u64;

__device__ __forceinline__ u64 splat2(float a) {
    u64 r; asm("mov.b64 %0,{%1,%1};" : "=l"(r) : "f"(a)); return r;
}
__device__ __forceinline__ float2 up2(u64 v) {
    float2 r; asm("mov.b64 {%0,%1},%2;" : "=f"(r.x), "=f"(r.y) : "l"(v)); return r;
}
__device__ __forceinline__ void fma2(u64& d, u64 a, u64 b) {
    asm("fma.rn.f32x2 %0,%1,%2,%0;" : "+l"(d) : "l"(a), "l"(b));
}
__device__ __forceinline__ float sig(float v) { return 1.0f / (1.0f + __expf(-v)); }

__device__ __forceinline__ void cpasync16(unsigned smem_addr, const void* gptr) {
    asm volatile("cp.async.cg.shared.global [%0], [%1], 16;"
                 :: "r"(smem_addr), "l"(gptr));
}
__device__ __forceinline__ void cp_commit() { asm volatile("cp.async.commit_group;"); }
__device__ __forceinline__ void cp_wait0()  { asm volatile("cp.async.wait_group 0;"); }

// Fused GRU cell:
//   r = sigmoid([x|h]@wr + br); z = sigmoid([x|h]@wz + bz)
//   g = tanh([x | r*h] @ [whx; whh] + bh)
//   h_out = h + z*(g - h)
__global__ void __launch_bounds__(NT, 1)
gru_fused2(const float* __restrict__ x,   const float* __restrict__ hp,
           const float* __restrict__ wr,  const float* __restrict__ wz,
           const float* __restrict__ whh, const float* __restrict__ whx,
           const float* __restrict__ br,  const float* __restrict__ bz,
           const float* __restrict__ bh,  float* __restrict__ out)
{
    extern __shared__ float sm[];
    float* sA = sm;                 // [BM][K1]: cols 0..255 = x, 256..511 = h (later r*h)
    float* sW = sm + SA_FLOATS;     // 2 buffers x W1TILE

    const int tid  = threadIdx.x;
    const int txc  = tid & 63;          // 64 column groups
    const int tyr  = tid >> 6;          // 8 row groups
    const int row0 = blockIdx.x * BM;
    const int rA   = tyr * 8;           // this thread's 8 contiguous rows
    const int c0   = 2 * txc;           // p=0 col; p=1 col = c0+128

    const unsigned sWu = (unsigned)__cvta_generic_to_shared(sW);

    // Per-thread static cp.async slots for GEMM1 tiles (4 x 16B)
    int g1_dst[4]; const float* g1_src[4];
    #pragma unroll
    for (int q = 0; q < 4; q++) {
        int j = tid + q * NT;               // 0..2047
        int gate = j >> 10, rem = j & 1023;
        int kr = rem >> 6, c = (rem & 63) << 2;
        g1_dst[q] = gate * (KT * H_DIM) + kr * H_DIM + c;       // floats
        g1_src[q] = (gate ? wz : wr) + kr * H_DIM + c;          // + kt*H_DIM per tile
    }
    // GEMM2 slots (2 x 16B)
    int g2_dst[2], g2_off[2];
    #pragma unroll
    for (int q = 0; q < 2; q++) {
        int j = tid + q * NT;               // 0..1023
        int kr = j >> 6, c = (j & 63) << 2;
        g2_dst[q] = kr * H_DIM + c;
        g2_off[q] = kr * H_DIM + c;
    }

    // ---- kick off weight tile 0 (async), then stage A = [x|h] ----
    #pragma unroll
    for (int q = 0; q < 4; q++)
        cpasync16(sWu + (unsigned)(g1_dst[q] * 4), g1_src[q]);
    cp_commit();

    #pragma unroll
    for (int t = 0; t < 8; t++) {
        int i = tid + t * NT;
        int r = i >> 6, c = (i & 63) << 2;
        *(float4*)&sA[r * K1 + c]          = *(const float4*)&x [(row0 + r) * IN_DIM + c];
        *(float4*)&sA[r * K1 + IN_DIM + c] = *(const float4*)&hp[(row0 + r) * H_DIM  + c];
    }
    cp_wait0();
    __syncthreads();

    // ================= GEMM1: r and z gates (shared A operand) =================
    u64 accr[8][2], accz[8][2];
    #pragma unroll
    for (int i = 0; i < 8; i++) { accr[i][0] = accr[i][1] = 0ull; accz[i][0] = accz[i][1] = 0ull; }

    for (int t = 0; t < NTILES; t++) {
        // prefetch tile t+1 into the other buffer (its readers passed barrier t-1)
        if (t + 1 < NTILES) {
            unsigned dstb = sWu + (unsigned)(((t + 1) & 1) * W1TILE * 4);
            #pragma unroll
            for (int q = 0; q < 4; q++)
                cpasync16(dstb + (unsigned)(g1_dst[q] * 4), g1_src[q] + (t + 1) * KT * H_DIM);
            cp_commit();
        }
        const float* W = sW + (t & 1) * W1TILE;
        const int ktb = t * KT;
        #pragma unroll
        for (int kk = 0; kk < KT; kk += 2) {
            u64 w00 = *(const u64*)&W[kk * H_DIM + c0];
            u64 w01 = *(const u64*)&W[(kk + 1) * H_DIM + c0];
            u64 z00 = *(const u64*)&W[KT * H_DIM + kk * H_DIM + c0];
            u64 z01 = *(const u64*)&W[KT * H_DIM + (kk + 1) * H_DIM + c0];
            u64 w10 = *(const u64*)&W[kk * H_DIM + c0 + 128];
            u64 w11 = *(const u64*)&W[(kk + 1) * H_DIM + c0 + 128];
            u64 z10 = *(const u64*)&W[KT * H_DIM + kk * H_DIM + c0 + 128];
            u64 z11 = *(const u64*)&W[KT * H_DIM + (kk + 1) * H_DIM + c0 + 128];
            #pragma unroll
            for (int i = 0; i < 8; i++) {
                float2 a = *(const float2*)&sA[(rA + i) * K1 + ktb + kk];
                u64 s0 = splat2(a.x), s1 = splat2(a.y);
                fma2(accr[i][0], s0, w00); fma2(accr[i][0], s1, w01);
                fma2(accz[i][0], s0, z00); fma2(accz[i][0], s1, z01);
                fma2(accr[i][1], s0, w10); fma2(accr[i][1], s1, w11);
                fma2(accz[i][1], s0, z10); fma2(accz[i][1], s1, z11);
            }
        }
        cp_wait0();
        __syncthreads();
    }

    // ---- epilogue 1: r,z; z stays in regs; overwrite sA h-half with r*h ----
    // start GEMM2 tile 0 load first (buf0's last readers finished at barrier t=30)
    #pragma unroll
    for (int q = 0; q < 2; q++)
        cpasync16(sWu + (unsigned)(g2_dst[q] * 4), whx + g2_off[q]);
    cp_commit();

    float2 zk[8][2];
    #pragma unroll
    for (int p = 0; p < 2; p++) {
        int col = c0 + 128 * p;
        float b_r0 = br[col], b_r1 = br[col + 1];
        float b_z0 = bz[col], b_z1 = bz[col + 1];
        #pragma unroll
        for (int i = 0; i < 8; i++) {
            int r = rA + i;
            float2 cr = up2(accr[i][p]);
            float2 cz = up2(accz[i][p]);
            float rg0 = sig(cr.x + b_r0);
            float rg1 = sig(cr.y + b_r1);
            zk[i][p].x = sig(cz.x + b_z0);
            zk[i][p].y = sig(cz.y + b_z1);
            float2 h2 = *(const float2*)&sA[r * K1 + IN_DIM + col];
            *(float2*)&sA[r * K1 + IN_DIM + col] = make_float2(rg0 * h2.x, rg1 * h2.y);
        }
    }
    cp_wait0();
    __syncthreads();

    // ================= GEMM2: [x | r*h] @ [whx; whh] =================
    u64 acc2[8][2];
    #pragma unroll
    for (int i = 0; i < 8; i++) { acc2[i][0] = acc2[i][1] = 0ull; }

    for (int t = 0; t < NTILES; t++) {
        if (t + 1 < NTILES) {
            int t1 = t + 1;
            const float* src = (t1 < 16) ? (whx + t1 * KT * H_DIM)
                                         : (whh + (t1 - 16) * KT * H_DIM);
            unsigned dstb = sWu + (unsigned)((t1 & 1) * W1TILE * 4);
            #pragma unroll
            for (int q = 0; q < 2; q++)
                cpasync16(dstb + (unsigned)(g2_dst[q] * 4), src + g2_off[q]);
            cp_commit();
        }
        const float* W = sW + (t & 1) * W1TILE;
        const int ktb = t * KT;
        #pragma unroll
        for (int kk = 0; kk < KT; kk += 2) {
            u64 w00 = *(const u64*)&W[kk * H_DIM + c0];
            u64 w01 = *(const u64*)&W[(kk + 1) * H_DIM + c0];
            u64 w10 = *(const u64*)&W[kk * H_DIM + c0 + 128];
            u64 w11 = *(const u64*)&W[(kk + 1) * H_DIM + c0 + 128];
            #pragma unroll
            for (int i = 0; i < 8; i++) {
                float2 a = *(const float2*)&sA[(rA + i) * K1 + ktb + kk];
                u64 s0 = splat2(a.x), s1 = splat2(a.y);
                fma2(acc2[i][0], s0, w00); fma2(acc2[i][0], s1, w01);
                fma2(acc2[i][1], s0, w10); fma2(acc2[i][1], s1, w11);
            }
        }
        cp_wait0();
        __syncthreads();
    }

    // ---- final epilogue: g = tanh(.+bh); h_out = h + z*(g-h); h re-read from global ----
    #pragma unroll
    for (int p = 0; p < 2; p++) {
        int col = c0 + 128 * p;
        float b_h0 = bh[col], b_h1 = bh[col + 1];
        #pragma unroll
        for (int i = 0; i < 8; i++) {
            int r = rA + i;
            float2 c2 = up2(acc2[i][p]);
            float g0 = tanhf(c2.x + b_h0);
            float g1 = tanhf(c2.y + b_h1);
            float2 h2 = *(const float2*)&hp[(row0 + r) * H_DIM + col];
            float o0 = h2.x + zk[i][p].x * (g0 - h2.x);
            float o1 = h2.y + zk[i][p].y * (g1 - h2.y);
            *(float2*)&out[(row0 + r) * H_DIM + col] = make_float2(o0, o1);
        }
    }
}

extern "C" void kernel_launch(void* const* d_in, const int* in_sizes, int n_in,
                              void* d_out, int out_size)
{
    const float* x   = (const float*)d_in[0];
    const float* hp  = (const float*)d_in[1];
    const float* wr  = (const float*)d_in[2];
    const float* wz  = (const float*)d_in[3];
    const float* whh = (const float*)d_in[4];
    const float* whx = (const float*)d_in[5];
    const float* br  = (const float*)d_in[6];
    const float* bz  = (const float*)d_in[7];
    const float* bh  = (const float*)d_in[8];

    size_t smem = (size_t)(SA_FLOATS + 2 * W1TILE) * sizeof(float); // 192 KB
    cudaFuncSetAttribute(gru_fused2,
                         cudaFuncAttributeMaxDynamicSharedMemorySize, (int)smem);
    gru_fused2<<<32768 / BM, NT, smem>>>(
        x, hp, wr, wz, whh, whx, br, bz, bh, (float*)d_out);
}